// round 1
// baseline (speedup 1.0000x reference)
#include <cuda_runtime.h>
#include <math.h>

// ---------------------------------------------------------------------------
// ThresholdMoeLayer: gate (softmax+threshold+renorm) -> H = X@A_cat (scaled by
// gate weights) -> Out = Hw @ B_cat.  All fp32.
//
// Shapes: X[N=65536, D=1024], gate_w[D,8], gate_b[8],
//         lora_A[8,1024,64] (per-expert [D,R] row-major slabs),
//         lora_B[8,64,1024] == row-major [512,1024] concatenation.
// ---------------------------------------------------------------------------

static constexpr int D_MODEL = 1024;
static constexpr int N_EXP   = 8;
static constexpr int RANK    = 64;
static constexpr int HCOLS   = N_EXP * RANK;   // 512
static constexpr int MAX_TOK = 65536;

// Scratch (no cudaMalloc allowed): gate weights + weighted hidden activations.
__device__ float g_w[MAX_TOK * N_EXP];                    // 2 MB
__device__ float g_h[(size_t)MAX_TOK * HCOLS];            // 134 MB

// ---------------------------------------------------------------------------
// Gate kernel: one warp per token. Computes softmax(x@gw + gb), thresholds at
// 0.1, renormalizes, writes w[n][8].
// ---------------------------------------------------------------------------
__global__ void gate_kernel(const float* __restrict__ x,
                            const float* __restrict__ gw,
                            const float* __restrict__ gb,
                            int n_tok) {
    int warp = (blockIdx.x * blockDim.x + threadIdx.x) >> 5;
    int lane = threadIdx.x & 31;
    if (warp >= n_tok) return;

    const float* xr = x + (size_t)warp * D_MODEL;
    float acc[N_EXP];
#pragma unroll
    for (int e = 0; e < N_EXP; e++) acc[e] = 0.f;

    for (int d = lane; d < D_MODEL; d += 32) {
        float xv = xr[d];
        const float* gwr = gw + d * N_EXP;
#pragma unroll
        for (int e = 0; e < N_EXP; e++) acc[e] = fmaf(xv, gwr[e], acc[e]);
    }
#pragma unroll
    for (int e = 0; e < N_EXP; e++) {
#pragma unroll
        for (int off = 16; off; off >>= 1)
            acc[e] += __shfl_xor_sync(0xffffffffu, acc[e], off);
    }
    if (lane == 0) {
        float m = -1e30f;
#pragma unroll
        for (int e = 0; e < N_EXP; e++) { acc[e] += gb[e]; m = fmaxf(m, acc[e]); }
        float s = 0.f;
#pragma unroll
        for (int e = 0; e < N_EXP; e++) { acc[e] = expf(acc[e] - m); s += acc[e]; }
        float inv = 1.f / s;
        float ws = 0.f;
#pragma unroll
        for (int e = 0; e < N_EXP; e++) {
            float g = acc[e] * inv;
            g = (g >= 0.1f) ? g : 0.f;
            acc[e] = g;
            ws += g;
        }
        float invw = (ws == 0.f) ? 1.f : (1.f / ws);
#pragma unroll
        for (int e = 0; e < N_EXP; e++)
            g_w[(size_t)warp * N_EXP + e] = acc[e] * invw;
    }
}

// ---------------------------------------------------------------------------
// GEMM1: Hw[n, e*64 + r] = w[n,e] * sum_d X[n,d] * A[e,d,r]
// Tile 128x64xK16, 256 threads, 8x4 microtile (rows split 4+4).
// Grid: (N/128, 8)
// ---------------------------------------------------------------------------
__global__ __launch_bounds__(256) void gemm1_kernel(const float* __restrict__ X,
                                                    const float* __restrict__ A) {
    __shared__ float Xs[16][132];   // +4 pad (transposed stores)
    __shared__ float As[16][64];
    __shared__ float ws[128];

    const int e   = blockIdx.y;
    const int n0  = blockIdx.x * 128;
    const int tid = threadIdx.x;
    const int ty  = tid >> 4;        // 0..15
    const int tx  = tid & 15;        // 0..15
    const float* Ae = A + (size_t)e * (D_MODEL * RANK);

    if (tid < 128) ws[tid] = g_w[(size_t)(n0 + tid) * N_EXP + e];

    // loader indices
    const int xr = tid >> 2;           // 0..63 (also +64)
    const int xk = (tid & 3) << 2;     // 0,4,8,12
    const int ar = tid >> 4;           // 0..15
    const int ac = (tid & 15) << 2;    // 0..60

    float acc[8][4];
#pragma unroll
    for (int i = 0; i < 8; i++)
#pragma unroll
        for (int j = 0; j < 4; j++) acc[i][j] = 0.f;

    const float* xbase0 = X + (size_t)(n0 + xr) * D_MODEL + xk;
    const float* xbase1 = xbase0 + (size_t)64 * D_MODEL;
    const float* abase  = Ae + (size_t)ar * RANK + ac;

    float4 rx0 = *(const float4*)(xbase0);
    float4 rx1 = *(const float4*)(xbase1);
    float4 ra  = *(const float4*)(abase);

    for (int k0 = 0; k0 < D_MODEL; k0 += 16) {
        Xs[xk + 0][xr] = rx0.x; Xs[xk + 1][xr] = rx0.y;
        Xs[xk + 2][xr] = rx0.z; Xs[xk + 3][xr] = rx0.w;
        Xs[xk + 0][xr + 64] = rx1.x; Xs[xk + 1][xr + 64] = rx1.y;
        Xs[xk + 2][xr + 64] = rx1.z; Xs[xk + 3][xr + 64] = rx1.w;
        *(float4*)&As[ar][ac] = ra;
        __syncthreads();

        if (k0 + 16 < D_MODEL) {
            rx0 = *(const float4*)(xbase0 + k0 + 16);
            rx1 = *(const float4*)(xbase1 + k0 + 16);
            ra  = *(const float4*)(abase + (size_t)(k0 + 16) * RANK);
        }

#pragma unroll
        for (int kk = 0; kk < 16; kk++) {
            float a0[4], a1[4], b[4];
            *(float4*)a0 = *(const float4*)&Xs[kk][ty * 4];
            *(float4*)a1 = *(const float4*)&Xs[kk][64 + ty * 4];
            *(float4*)b  = *(const float4*)&As[kk][tx * 4];
#pragma unroll
            for (int i = 0; i < 4; i++)
#pragma unroll
                for (int j = 0; j < 4; j++) {
                    acc[i][j]     = fmaf(a0[i], b[j], acc[i][j]);
                    acc[4 + i][j] = fmaf(a1[i], b[j], acc[4 + i][j]);
                }
        }
        __syncthreads();
    }

    // epilogue: scale by gate weight, write Hw
#pragma unroll
    for (int i = 0; i < 4; i++) {
        int r = ty * 4 + i;
        float w = ws[r];
        float4 o0 = { acc[i][0] * w, acc[i][1] * w, acc[i][2] * w, acc[i][3] * w };
        *(float4*)(g_h + (size_t)(n0 + r) * HCOLS + e * RANK + tx * 4) = o0;
        r = 64 + ty * 4 + i;
        w = ws[r];
        float4 o1 = { acc[4 + i][0] * w, acc[4 + i][1] * w, acc[4 + i][2] * w, acc[4 + i][3] * w };
        *(float4*)(g_h + (size_t)(n0 + r) * HCOLS + e * RANK + tx * 4) = o1;
    }
}

// ---------------------------------------------------------------------------
// GEMM2: Out[N,1024] = Hw[N,512] @ Bcat[512,1024]
// Tile 128x128xK16, 256 threads, 8x8 microtile (rows/cols split 4+4).
// Grid: (N/128, 1024/128)
// ---------------------------------------------------------------------------
__global__ __launch_bounds__(256) void gemm2_kernel(const float* __restrict__ Bc,
                                                    float* __restrict__ out) {
    __shared__ float Hs[16][132];   // +4 pad
    __shared__ float Bs[16][128];

    const int n0  = blockIdx.x * 128;
    const int c0  = blockIdx.y * 128;
    const int tid = threadIdx.x;
    const int ty  = tid >> 4;
    const int tx  = tid & 15;

    const int hr = tid >> 2;           // 0..63 (also +64)
    const int hk = (tid & 3) << 2;     // 0,4,8,12
    const int br = tid >> 5;           // 0..7 (also +8)
    const int bc = (tid & 31) << 2;    // 0..124

    float acc[8][8];
#pragma unroll
    for (int i = 0; i < 8; i++)
#pragma unroll
        for (int j = 0; j < 8; j++) acc[i][j] = 0.f;

    const float* hbase0 = g_h + (size_t)(n0 + hr) * HCOLS + hk;
    const float* hbase1 = hbase0 + (size_t)64 * HCOLS;
    const float* bbase0 = Bc + (size_t)br * D_MODEL + c0 + bc;
    const float* bbase1 = bbase0 + (size_t)8 * D_MODEL;

    float4 rh0 = *(const float4*)(hbase0);
    float4 rh1 = *(const float4*)(hbase1);
    float4 rb0 = *(const float4*)(bbase0);
    float4 rb1 = *(const float4*)(bbase1);

    for (int k0 = 0; k0 < HCOLS; k0 += 16) {
        Hs[hk + 0][hr] = rh0.x; Hs[hk + 1][hr] = rh0.y;
        Hs[hk + 2][hr] = rh0.z; Hs[hk + 3][hr] = rh0.w;
        Hs[hk + 0][hr + 64] = rh1.x; Hs[hk + 1][hr + 64] = rh1.y;
        Hs[hk + 2][hr + 64] = rh1.z; Hs[hk + 3][hr + 64] = rh1.w;
        *(float4*)&Bs[br][bc]     = rb0;
        *(float4*)&Bs[br + 8][bc] = rb1;
        __syncthreads();

        if (k0 + 16 < HCOLS) {
            rh0 = *(const float4*)(hbase0 + k0 + 16);
            rh1 = *(const float4*)(hbase1 + k0 + 16);
            rb0 = *(const float4*)(bbase0 + (size_t)(k0 + 16) * D_MODEL);
            rb1 = *(const float4*)(bbase1 + (size_t)(k0 + 16) * D_MODEL);
        }

#pragma unroll
        for (int kk = 0; kk < 16; kk++) {
            float a0[4], a1[4], b0[4], b1[4];
            *(float4*)a0 = *(const float4*)&Hs[kk][ty * 4];
            *(float4*)a1 = *(const float4*)&Hs[kk][64 + ty * 4];
            *(float4*)b0 = *(const float4*)&Bs[kk][tx * 4];
            *(float4*)b1 = *(const float4*)&Bs[kk][64 + tx * 4];
#pragma unroll
            for (int i = 0; i < 4; i++)
#pragma unroll
                for (int j = 0; j < 4; j++) {
                    acc[i][j]         = fmaf(a0[i], b0[j], acc[i][j]);
                    acc[i][4 + j]     = fmaf(a0[i], b1[j], acc[i][4 + j]);
                    acc[4 + i][j]     = fmaf(a1[i], b0[j], acc[4 + i][j]);
                    acc[4 + i][4 + j] = fmaf(a1[i], b1[j], acc[4 + i][4 + j]);
                }
        }
        __syncthreads();
    }

#pragma unroll
    for (int i = 0; i < 4; i++) {
        int r = n0 + ty * 4 + i;
        *(float4*)(out + (size_t)r * D_MODEL + c0 + tx * 4)      = *(float4*)&acc[i][0];
        *(float4*)(out + (size_t)r * D_MODEL + c0 + 64 + tx * 4) = *(float4*)&acc[i][4];
        r = n0 + 64 + ty * 4 + i;
        *(float4*)(out + (size_t)r * D_MODEL + c0 + tx * 4)      = *(float4*)&acc[4 + i][0];
        *(float4*)(out + (size_t)r * D_MODEL + c0 + 64 + tx * 4) = *(float4*)&acc[4 + i][4];
    }
}

// ---------------------------------------------------------------------------
extern "C" void kernel_launch(void* const* d_in, const int* in_sizes, int n_in,
                              void* d_out, int out_size) {
    const float* x  = (const float*)d_in[0];
    const float* gw = (const float*)d_in[1];
    const float* gb = (const float*)d_in[2];
    const float* la = (const float*)d_in[3];
    const float* lb = (const float*)d_in[4];
    float* out = (float*)d_out;

    int n_tok = in_sizes[0] / D_MODEL;   // 65536

    // gate: one warp per token, 8 warps per block
    gate_kernel<<<(n_tok + 7) / 8, 256>>>(x, gw, gb, n_tok);

    dim3 g1(n_tok / 128, N_EXP);
    gemm1_kernel<<<g1, 256>>>(x, la);

    dim3 g2(n_tok / 128, D_MODEL / 128);
    gemm2_kernel<<<g2, 256>>>(lb, out);
}

// round 4
// speedup vs baseline: 1.6212x; 1.6212x over previous
#include <cuda_runtime.h>
#include <mma.h>
#include <math.h>

using namespace nvcuda;

// ---------------------------------------------------------------------------
// ThresholdMoeLayer:
//   gate (fp32, exact)  -> w[N,8]
//   GEMM1 (tf32 TC):  g_h[n, e*64+r] = (w[n,e] * X[n,:]) @ A_e      [N,512]
//   GEMM2 (tf32 TC):  out = g_h @ B_cat[512,1024]
// X[65536,1024], gate_w[1024,8], lora_A[8,1024,64], lora_B[8,64,1024]
// ---------------------------------------------------------------------------

static constexpr int D_MODEL = 1024;
static constexpr int N_EXP   = 8;
static constexpr int RANK    = 64;
static constexpr int HCOLS   = N_EXP * RANK;   // 512
static constexpr int MAX_TOK = 65536;

__device__ float g_w[MAX_TOK * N_EXP];            // gate weights
__device__ float g_h[(size_t)MAX_TOK * HCOLS];    // weighted hidden

// ---------------------------------------------------------------------------
// Gate kernel (fp32): 256 threads, 2 tokens/thread, gate_w cached in smem.
// ---------------------------------------------------------------------------
__global__ __launch_bounds__(256) void gate_kernel(const float* __restrict__ x,
                                                   const float* __restrict__ gw,
                                                   const float* __restrict__ gb,
                                                   int n_tok) {
    __shared__ float gws[D_MODEL * N_EXP];   // 32 KB
    __shared__ float gbs[N_EXP];
    const int tid = threadIdx.x;

    for (int i = tid * 4; i < D_MODEL * N_EXP; i += 256 * 4)
        *(float4*)&gws[i] = *(const float4*)&gw[i];
    if (tid < N_EXP) gbs[tid] = gb[tid];
    __syncthreads();

    const int n0 = blockIdx.x * 512;
    const int t0 = n0 + tid;
    const int t1 = t0 + 256;
    if (t0 >= n_tok) return;
    const bool have1 = (t1 < n_tok);

    const float* xr0 = x + (size_t)t0 * D_MODEL;
    const float* xr1 = x + (size_t)t1 * D_MODEL;

    float acc0[N_EXP], acc1[N_EXP];
#pragma unroll
    for (int e = 0; e < N_EXP; e++) { acc0[e] = 0.f; acc1[e] = 0.f; }

    for (int d0 = 0; d0 < D_MODEL; d0 += 4) {
        float va[4], vb[4];
        *(float4*)va = *(const float4*)(xr0 + d0);
        *(float4*)vb = have1 ? *(const float4*)(xr1 + d0) : make_float4(0,0,0,0);
#pragma unroll
        for (int dd = 0; dd < 4; dd++) {
            float g[8];
            *(float4*)&g[0] = *(const float4*)&gws[(d0 + dd) * N_EXP];
            *(float4*)&g[4] = *(const float4*)&gws[(d0 + dd) * N_EXP + 4];
            float xa = va[dd], xb = vb[dd];
#pragma unroll
            for (int e = 0; e < N_EXP; e++) {
                acc0[e] = fmaf(xa, g[e], acc0[e]);
                acc1[e] = fmaf(xb, g[e], acc1[e]);
            }
        }
    }

#pragma unroll
    for (int t = 0; t < 2; t++) {
        if (t == 1 && !have1) break;
        float* acc = (t == 0) ? acc0 : acc1;
        int tok = (t == 0) ? t0 : t1;
        float m = -1e30f;
#pragma unroll
        for (int e = 0; e < N_EXP; e++) { acc[e] += gbs[e]; m = fmaxf(m, acc[e]); }
        float s = 0.f;
#pragma unroll
        for (int e = 0; e < N_EXP; e++) { acc[e] = expf(acc[e] - m); s += acc[e]; }
        float inv = 1.f / s;
        float ws = 0.f;
#pragma unroll
        for (int e = 0; e < N_EXP; e++) {
            float gg = acc[e] * inv;
            gg = (gg >= 0.1f) ? gg : 0.f;
            acc[e] = gg;
            ws += gg;
        }
        float invw = (ws == 0.f) ? 1.f : (1.f / ws);
#pragma unroll
        for (int e = 0; e < N_EXP; e++)
            g_w[(size_t)tok * N_EXP + e] = acc[e] * invw;
    }
}

// ---------------------------------------------------------------------------
// GEMM1 (tf32): block = 128 tokens x 64 cols (one expert), K = 1024.
// Gate weight fused by scaling X rows at smem-store time.
// Grid: (8 experts, N/128) — expert-major so X tiles reuse in L2.
// ---------------------------------------------------------------------------
__global__ __launch_bounds__(256, 2) void gemm1_kernel(const float* __restrict__ X,
                                                       const float* __restrict__ A) {
    __shared__ float Xs[128][36];
    __shared__ float As[32][72];
    __shared__ float ws[128];

    const int e   = blockIdx.x;
    const int n0  = blockIdx.y * 128;
    const int tid = threadIdx.x;
    const int warp = tid >> 5;
    const int wm = warp & 3;          // 0..3 : rows wm*32
    const int wn = warp >> 2;         // 0..1 : cols wn*32
    const float* Ae = A + (size_t)e * (D_MODEL * RANK);

    if (tid < 128) ws[tid] = g_w[(size_t)(n0 + tid) * N_EXP + e];

    const int xr = tid >> 3;          // 0..31
    const int xk = (tid & 7) << 2;    // 0..28
    const int ar = tid >> 4;          // 0..15
    const int ac = (tid & 15) << 2;   // 0..60

    const float* xb = X + (size_t)(n0 + xr) * D_MODEL + xk;
    const float* ab = Ae + (size_t)ar * RANK + ac;

    float4 rx[4], ra[2];
#pragma unroll
    for (int i = 0; i < 4; i++) rx[i] = *(const float4*)(xb + (size_t)(32 * i) * D_MODEL);
    ra[0] = *(const float4*)(ab);
    ra[1] = *(const float4*)(ab + 16 * RANK);

    wmma::fragment<wmma::accumulator, 16, 16, 8, float> c[2][2];
#pragma unroll
    for (int i = 0; i < 2; i++)
#pragma unroll
        for (int j = 0; j < 2; j++) wmma::fill_fragment(c[i][j], 0.f);

    __syncthreads();   // ws ready

    for (int k0 = 0; k0 < D_MODEL; k0 += 32) {
#pragma unroll
        for (int i = 0; i < 4; i++) {
            int r = xr + 32 * i;
            float w = ws[r];
            Xs[r][xk + 0] = wmma::__float_to_tf32(rx[i].x * w);
            Xs[r][xk + 1] = wmma::__float_to_tf32(rx[i].y * w);
            Xs[r][xk + 2] = wmma::__float_to_tf32(rx[i].z * w);
            Xs[r][xk + 3] = wmma::__float_to_tf32(rx[i].w * w);
        }
#pragma unroll
        for (int i = 0; i < 2; i++) {
            As[ar + 16 * i][ac + 0] = wmma::__float_to_tf32((&ra[i].x)[0]);
            As[ar + 16 * i][ac + 1] = wmma::__float_to_tf32((&ra[i].x)[1]);
            As[ar + 16 * i][ac + 2] = wmma::__float_to_tf32((&ra[i].x)[2]);
            As[ar + 16 * i][ac + 3] = wmma::__float_to_tf32((&ra[i].x)[3]);
        }
        __syncthreads();

        if (k0 + 32 < D_MODEL) {
#pragma unroll
            for (int i = 0; i < 4; i++)
                rx[i] = *(const float4*)(xb + (size_t)(32 * i) * D_MODEL + k0 + 32);
            ra[0] = *(const float4*)(ab + (size_t)(k0 + 32) * RANK);
            ra[1] = *(const float4*)(ab + (size_t)(k0 + 32 + 16) * RANK);
        }

#pragma unroll
        for (int kk = 0; kk < 4; kk++) {
            wmma::fragment<wmma::matrix_a, 16, 16, 8, wmma::precision::tf32, wmma::row_major> a[2];
            wmma::fragment<wmma::matrix_b, 16, 16, 8, wmma::precision::tf32, wmma::row_major> b[2];
#pragma unroll
            for (int i = 0; i < 2; i++)
                wmma::load_matrix_sync(a[i], &Xs[wm * 32 + i * 16][kk * 8], 36);
#pragma unroll
            for (int j = 0; j < 2; j++)
                wmma::load_matrix_sync(b[j], &As[kk * 8][wn * 32 + j * 16], 72);
#pragma unroll
            for (int i = 0; i < 2; i++)
#pragma unroll
                for (int j = 0; j < 2; j++)
                    wmma::mma_sync(c[i][j], a[i], b[j], c[i][j]);
        }
        __syncthreads();
    }

#pragma unroll
    for (int i = 0; i < 2; i++)
#pragma unroll
        for (int j = 0; j < 2; j++)
            wmma::store_matrix_sync(
                g_h + (size_t)(n0 + wm * 32 + i * 16) * HCOLS + e * RANK + wn * 32 + j * 16,
                c[i][j], HCOLS, wmma::mem_row_major);
}

// ---------------------------------------------------------------------------
// GEMM2 (tf32): Out[N,1024] = g_h[N,512] @ Bcat[512,1024]
// Block 128x128, K=512; 8 warps (4m x 2n), warp 32x64.
// ---------------------------------------------------------------------------
__global__ __launch_bounds__(256, 2) void gemm2_kernel(const float* __restrict__ Bc,
                                                       float* __restrict__ out) {
    __shared__ float Hs[128][36];
    __shared__ float Bs[32][136];

    const int n0  = blockIdx.x * 128;
    const int c0  = blockIdx.y * 128;
    const int tid = threadIdx.x;
    const int warp = tid >> 5;
    const int wm = warp & 3;          // rows wm*32
    const int wn = warp >> 2;         // cols wn*64

    const int hr = tid >> 3;          // 0..31
    const int hk = (tid & 7) << 2;    // 0..28
    const int br = tid >> 5;          // 0..7
    const int bc = (tid & 31) << 2;   // 0..124

    const float* hb = g_h + (size_t)(n0 + hr) * HCOLS + hk;
    const float* bb = Bc + (size_t)br * D_MODEL + c0 + bc;

    float4 rh[4], rb[4];
#pragma unroll
    for (int i = 0; i < 4; i++) rh[i] = *(const float4*)(hb + (size_t)(32 * i) * HCOLS);
#pragma unroll
    for (int i = 0; i < 4; i++) rb[i] = *(const float4*)(bb + (size_t)(8 * i) * D_MODEL);

    wmma::fragment<wmma::accumulator, 16, 16, 8, float> c[2][4];
#pragma unroll
    for (int i = 0; i < 2; i++)
#pragma unroll
        for (int j = 0; j < 4; j++) wmma::fill_fragment(c[i][j], 0.f);

    for (int k0 = 0; k0 < HCOLS; k0 += 32) {
#pragma unroll
        for (int i = 0; i < 4; i++) {
            int r = hr + 32 * i;
            Hs[r][hk + 0] = wmma::__float_to_tf32(rh[i].x);
            Hs[r][hk + 1] = wmma::__float_to_tf32(rh[i].y);
            Hs[r][hk + 2] = wmma::__float_to_tf32(rh[i].z);
            Hs[r][hk + 3] = wmma::__float_to_tf32(rh[i].w);
        }
#pragma unroll
        for (int i = 0; i < 4; i++) {
            int r = br + 8 * i;
            Bs[r][bc + 0] = wmma::__float_to_tf32(rb[i].x);
            Bs[r][bc + 1] = wmma::__float_to_tf32(rb[i].y);
            Bs[r][bc + 2] = wmma::__float_to_tf32(rb[i].z);
            Bs[r][bc + 3] = wmma::__float_to_tf32(rb[i].w);
        }
        __syncthreads();

        if (k0 + 32 < HCOLS) {
#pragma unroll
            for (int i = 0; i < 4; i++)
                rh[i] = *(const float4*)(hb + (size_t)(32 * i) * HCOLS + k0 + 32);
#pragma unroll
            for (int i = 0; i < 4; i++)
                rb[i] = *(const float4*)(bb + (size_t)(k0 + 32 + 8 * i) * D_MODEL);
        }

#pragma unroll
        for (int kk = 0; kk < 4; kk++) {
            wmma::fragment<wmma::matrix_a, 16, 16, 8, wmma::precision::tf32, wmma::row_major> a[2];
            wmma::fragment<wmma::matrix_b, 16, 16, 8, wmma::precision::tf32, wmma::row_major> b[4];
#pragma unroll
            for (int i = 0; i < 2; i++)
                wmma::load_matrix_sync(a[i], &Hs[wm * 32 + i * 16][kk * 8], 36);
#pragma unroll
            for (int j = 0; j < 4; j++)
                wmma::load_matrix_sync(b[j], &Bs[kk * 8][wn * 64 + j * 16], 136);
#pragma unroll
            for (int i = 0; i < 2; i++)
#pragma unroll
                for (int j = 0; j < 4; j++)
                    wmma::mma_sync(c[i][j], a[i], b[j], c[i][j]);
        }
        __syncthreads();
    }

#pragma unroll
    for (int i = 0; i < 2; i++)
#pragma unroll
        for (int j = 0; j < 4; j++)
            wmma::store_matrix_sync(
                out + (size_t)(n0 + wm * 32 + i * 16) * D_MODEL + c0 + wn * 64 + j * 16,
                c[i][j], D_MODEL, wmma::mem_row_major);
}

// ---------------------------------------------------------------------------
extern "C" void kernel_launch(void* const* d_in, const int* in_sizes, int n_in,
                              void* d_out, int out_size) {
    const float* x  = (const float*)d_in[0];
    const float* gw = (const float*)d_in[1];
    const float* gb = (const float*)d_in[2];
    const float* la = (const float*)d_in[3];
    const float* lb = (const float*)d_in[4];
    float* out = (float*)d_out;

    int n_tok = in_sizes[0] / D_MODEL;   // 65536

    gate_kernel<<<(n_tok + 511) / 512, 256>>>(x, gw, gb, n_tok);

    dim3 g1(N_EXP, n_tok / 128);
    gemm1_kernel<<<g1, 256>>>(x, la);

    dim3 g2(n_tok / 128, D_MODEL / 128);
    gemm2_kernel<<<g2, 256>>>(lb, out);
}